// round 15
// baseline (speedup 1.0000x reference)
#include <cuda_runtime.h>
#include <math_constants.h>
#include <cstdint>

// ---------------------------------------------------------------------------
// DetectionLoss on GB300 — round 13.
//
// R12 ncu: gather_kernel = 13.8us of 29.2us, occ 60%, issue 21%, all pipes
// idle => latency-chain bound. This round shortens the chain:
//   - cls row (80 f32 = 320B, 16B-aligned) loaded as 20 float4s (lanes 0-19)
//   - label logit extracted from those registers via shfl (removes the
//     dependent row[lab] LDG — a full second memory round-trip)
//   - gt box + label prefetched before the key merge (independent of j)
//   - argmin: unroll 8 (lower loop overhead); packed f32x2 scan + packed
//     recovery unchanged (validated bitwise: rel_err == 0.0 in R12)
// Structure: argmin writes per-chunk keys non-atomically; gather warp-merges,
// computes CE/L1, block partials, last-block deterministic fold.
// ---------------------------------------------------------------------------

#define BATCH   16
#define NGT     128
#define NC      80
#define HW0     25600
#define HW1     6400
#define HW2     1600
#define CHUNK   1024
#define C0      25              // ceil(HW0/CHUNK)
#define C1      7               // ceil(HW1/CHUNK)
#define C2      2               // ceil(HW2/CHUNK)
#define CPB     (C0 + C1 + C2)  // 34 chunk-blocks per batch
#define NMATCH  (3 * BATCH * NGT)   // 6144
#define GBLK    (NMATCH / 8)        // 768 gather blocks (8 warps each)

__device__ unsigned long long g_part[BATCH * CPB * NGT];  // per-chunk best keys
__device__ double g_pce[GBLK];
__device__ double g_pl1[GBLK];
__device__ double g_pw[GBLK];
__device__ unsigned int g_cnt;   // zero-initialized; finisher resets to 0

// ---- f32x2 packed helpers (sm_100+) ---------------------------------------
__device__ __forceinline__ unsigned long long pk2(float lo, float hi) {
    unsigned long long r;
    asm("mov.b64 %0, {%1,%2};" : "=l"(r) : "f"(lo), "f"(hi));
    return r;
}
__device__ __forceinline__ void upk2(unsigned long long v, float& lo, float& hi) {
    asm("mov.b64 {%0,%1}, %2;" : "=f"(lo), "=f"(hi) : "l"(v));
}
__device__ __forceinline__ unsigned long long add2(unsigned long long a, unsigned long long b) {
    unsigned long long d;
    asm("add.rn.f32x2 %0, %1, %2;" : "=l"(d) : "l"(a), "l"(b));
    return d;
}
__device__ __forceinline__ unsigned long long mul2(unsigned long long a, unsigned long long b) {
    unsigned long long d;
    asm("mul.rn.f32x2 %0, %1, %2;" : "=l"(d) : "l"(a), "l"(b));
    return d;
}
__device__ __forceinline__ unsigned long long fma2(unsigned long long a, unsigned long long b,
                                                   unsigned long long c) {
    unsigned long long d;
    asm("fma.rn.f32x2 %0, %1, %2, %3;" : "=l"(d) : "l"(a), "l"(b), "l"(c));
    return d;
}

// One packed d2 pair, exact fma form per lane. Used IDENTICALLY by scan and
// recovery -> bitwise-equal results by instruction determinism.
__device__ __forceinline__ unsigned long long d2pair(
    unsigned long long xpair, unsigned long long ypair,
    unsigned long long ngxx, unsigned long long ngyy)
{
    unsigned long long dx = add2(xpair, ngxx);
    unsigned long long dy = add2(ypair, ngyy);
    return fma2(dy, dy, mul2(dx, dx));
}

// ---------------------------------------------------------------------------
__global__ __launch_bounds__(128) void argmin_kernel(
    const float* __restrict__ r0, const float* __restrict__ r1,
    const float* __restrict__ r2, const float* __restrict__ gt)
{
    __shared__ __align__(16) float xs[CHUNK];
    __shared__ __align__(16) float ys[CHUNK];

    int bid = blockIdx.x;
    int b   = bid / CPB;
    int cid = bid % CPB;

    int chunk, hw;
    const float* reg;
    if (cid < C0)            { chunk = cid;            hw = HW0; reg = r0; }
    else if (cid < C0 + C1)  { chunk = cid - C0;       hw = HW1; reg = r1; }
    else                     { chunk = cid - C0 - C1;  hw = HW2; reg = r2; }

    int j0 = chunk * CHUNK;

    // one GT per thread: coalesced float4 load of its box (xy used)
    int n = threadIdx.x;
    float4 gbox = ((const float4*)gt)[(size_t)b * NGT + n];
    float ngx = -gbox.x, ngy = -gbox.y;   // (px-gx)^2 == (gx-px)^2 exactly
    unsigned long long ngxx = pk2(ngx, ngx);
    unsigned long long ngyy = pk2(ngy, ngy);

    // stage xy into SoA smem (pad tail with huge coords -> d2 huge)
    const float4* rp = (const float4*)(reg + (size_t)b * hw * 4);
    for (int t = threadIdx.x; t < CHUNK; t += 128) {
        int j = j0 + t;
        float x, y;
        if (j < hw) { float4 v = rp[j]; x = v.x; y = v.y; }
        else        { x = 3.0e30f; y = 3.0e30f; }
        xs[t] = x; ys[t] = y;
    }
    __syncthreads();

    float best  = CUDART_INF_F;
    int   basej = 0;

    const ulonglong2* xv = (const ulonglong2*)xs;
    const ulonglong2* yv = (const ulonglong2*)ys;

    #pragma unroll 8
    for (int t = 0; t < CHUNK; t += 8) {
        int i = t >> 2;
        ulonglong2 xa = xv[i], xb = xv[i + 1];   // packed (x[t],x[t+1]) ...
        ulonglong2 ya = yv[i], yb = yv[i + 1];

        unsigned long long d0 = d2pair(xa.x, ya.x, ngxx, ngyy);
        unsigned long long d1 = d2pair(xa.y, ya.y, ngxx, ngyy);
        unsigned long long d2 = d2pair(xb.x, yb.x, ngxx, ngyy);
        unsigned long long d3 = d2pair(xb.y, yb.y, ngxx, ngyy);

        float a0, a1, a2, a3, a4, a5, a6, a7;
        upk2(d0, a0, a1);
        upk2(d1, a2, a3);
        upk2(d2, a4, a5);
        upk2(d3, a6, a7);

        float m01 = fminf(a0, a1);
        float m23 = fminf(a2, a3);
        float m45 = fminf(a4, a5);
        float m67 = fminf(a6, a7);
        float m   = fminf(fminf(m01, m23), fminf(m45, m67));

        bool c = m < best;                 // strict < keeps earliest group
        best  = c ? m : best;
        basej = c ? t : basej;
    }

    // ---- index recovery: SAME packed instructions on SAME smem inputs ->
    // bit-identical recompute, == must hit. Descending order (pair 3..0,
    // hi before lo) => lowest offset wins on exact duplicates.
    int off = 0;
    {
        int i = basej >> 2;
        ulonglong2 xa = xv[i], xb = xv[i + 1];
        ulonglong2 ya = yv[i], yb = yv[i + 1];
        unsigned long long dp[4];
        dp[0] = d2pair(xa.x, ya.x, ngxx, ngyy);
        dp[1] = d2pair(xa.y, ya.y, ngxx, ngyy);
        dp[2] = d2pair(xb.x, yb.x, ngxx, ngyy);
        dp[3] = d2pair(xb.y, yb.y, ngxx, ngyy);
        #pragma unroll
        for (int p = 3; p >= 0; --p) {
            float lo, hi;
            upk2(dp[p], lo, hi);
            if (hi == best) off = 2 * p + 1;
            if (lo == best) off = 2 * p;       // lo checked after hi: lower wins
        }
    }

    int j = j0 + basej + off;
    unsigned long long key =
        ((unsigned long long)__float_as_uint(best) << 32) | (unsigned int)j;
    g_part[(size_t)bid * NGT + n] = key;   // non-atomic: every slot written
}

// ---------------------------------------------------------------------------
__global__ __launch_bounds__(256) void gather_kernel(
    const float* __restrict__ c0, const float* __restrict__ c1,
    const float* __restrict__ c2,
    const float* __restrict__ r0, const float* __restrict__ r1,
    const float* __restrict__ r2,
    const float* __restrict__ gt, const int* __restrict__ labels,
    float* __restrict__ out)
{
    __shared__ float s_ce[8], s_l1[8], s_w[8];
    __shared__ bool  s_last;

    int tid  = threadIdx.x;
    int wid  = (blockIdx.x * blockDim.x + tid) >> 5;   // global match id
    int wloc = tid >> 5;
    int lane = tid & 31;

    int lvl = wid / (BATCH * NGT);
    int rr  = wid % (BATCH * NGT);
    int b   = rr / NGT;
    int n   = rr % NGT;

    const float* cls; const float* reg; int hw, cbase, ccnt;
    if (lvl == 0)      { cls = c0; reg = r0; hw = HW0; cbase = 0;       ccnt = C0; }
    else if (lvl == 1) { cls = c1; reg = r1; hw = HW1; cbase = C0;      ccnt = C1; }
    else               { cls = c2; reg = r2; hw = HW2; cbase = C0 + C1; ccnt = C2; }

    // ---- prefetch everything that does NOT depend on the matched index -----
    float4 gb = ((const float4*)gt)[(size_t)b * NGT + n];   // broadcast load
    int    lab = labels[b * NGT + n];

    // ---- merge per-chunk partial keys: lane l holds chunk l's key ----------
    unsigned long long key = 0xFFFFFFFFFFFFFFFFULL;
    if (lane < ccnt)
        key = g_part[((size_t)b * CPB + cbase + lane) * NGT + n];
    #pragma unroll
    for (int s = 16; s; s >>= 1) {
        unsigned long long o = __shfl_xor_sync(0xFFFFFFFFu, key, s);
        key = o < key ? o : key;           // min d2, then min j (packed order)
    }

    float d2 = __uint_as_float((unsigned int)(key >> 32));
    int   j  = (int)(unsigned int)(key & 0xFFFFFFFFULL);

    float w = (__fsqrt_rn(d2) < 2.5f) ? 1.0f : 0.0f;

    // ---- matched row: 80 f32 = 20 float4 (rows are 320B => 16B aligned) ----
    const float4* row4 = (const float4*)(cls + ((size_t)b * hw + j) * NC);
    float4 v;
    if (lane < 20) v = row4[lane];
    else           v = make_float4(-CUDART_INF_F, -CUDART_INF_F,
                                   -CUDART_INF_F, -CUDART_INF_F);

    // matched reg row (independent of cls loads; issues concurrently)
    float4 pr;
    if (lane == 0) pr = ((const float4*)reg)[(size_t)b * hw + j];

    // ---- warp log-softmax over the 80 registers ----------------------------
    float mx = fmaxf(fmaxf(v.x, v.y), fmaxf(v.z, v.w));
    #pragma unroll
    for (int s = 16; s; s >>= 1) mx = fmaxf(mx, __shfl_xor_sync(0xFFFFFFFFu, mx, s));

    float se = 0.0f;
    if (lane < 20)
        se = expf(v.x - mx) + expf(v.y - mx) + expf(v.z - mx) + expf(v.w - mx);
    #pragma unroll
    for (int s = 16; s; s >>= 1) se += __shfl_xor_sync(0xFFFFFFFFu, se, s);

    // ---- label logit from registers via shuffle (no second global load) ----
    int   lcomp = lab & 3;
    float comp  = (lcomp == 0) ? v.x : (lcomp == 1) ? v.y : (lcomp == 2) ? v.z : v.w;
    float xl    = __shfl_sync(0xFFFFFFFFu, comp, lab >> 2);

    if (lane == 0) {
        float ce = (mx + logf(se)) - xl;
        float l1 = fabsf(pr.x - gb.x) + fabsf(pr.y - gb.y) +
                   fabsf(pr.z - gb.z) + fabsf(pr.w - gb.w);
        s_ce[wloc] = ce * w;
        s_l1[wloc] = l1 * w;
        s_w[wloc]  = w;
    }
    __syncthreads();

    // ---- deterministic block partial sum (fixed order, double) ------------
    if (tid == 0) {
        double pc = 0.0, pl = 0.0, pw = 0.0;
        #pragma unroll
        for (int i = 0; i < 8; ++i) {
            pc += (double)s_ce[i];
            pl += (double)s_l1[i];
            pw += (double)s_w[i];
        }
        g_pce[blockIdx.x] = pc;
        g_pl1[blockIdx.x] = pl;
        g_pw[blockIdx.x]  = pw;
        __threadfence();
        unsigned int vcnt = atomicAdd(&g_cnt, 1u);
        s_last = (vcnt == (unsigned int)(gridDim.x - 1));
    }
    __syncthreads();

    // ---- last block folds the 768 partials (fixed order => deterministic) --
    if (s_last) {
        __threadfence();
        __shared__ double rc[256], rl[256], rw[256];
        double pc = 0.0, pl = 0.0, pw = 0.0;
        for (int i = tid; i < GBLK; i += 256) {
            pc += g_pce[i];
            pl += g_pl1[i];
            pw += g_pw[i];
        }
        rc[tid] = pc; rl[tid] = pl; rw[tid] = pw;
        __syncthreads();
        for (int s = 128; s > 0; s >>= 1) {
            if (tid < s) {
                rc[tid] += rc[tid + s];
                rl[tid] += rl[tid + s];
                rw[tid] += rw[tid + s];
            }
            __syncthreads();
        }
        if (tid == 0) {
            double npos  = rw[0];
            double denom = npos > 1.0 ? npos : 1.0;
            out[0] = (float)(rc[0] / denom);
            out[1] = (float)(rl[0] / denom);
            out[2] = (float)npos;
            g_cnt  = 0;                    // self-reset for next graph replay
        }
    }
}

// ---------------------------------------------------------------------------
extern "C" void kernel_launch(void* const* d_in, const int* in_sizes, int n_in,
                              void* d_out, int out_size)
{
    // Resolve inputs BY SIZE (all 8 element counts are pairwise distinct).
    const float* c0 = 0; const float* c1 = 0; const float* c2 = 0;
    const float* r0 = 0; const float* r1 = 0; const float* r2 = 0;
    const float* gt = 0; const int* lb = 0;
    for (int i = 0; i < n_in; ++i) {
        long long s = in_sizes[i];
        void* p = d_in[i];
        if      (s == (long long)BATCH * HW0 * NC) c0 = (const float*)p;  // 32,768,000
        else if (s == (long long)BATCH * HW1 * NC) c1 = (const float*)p;  //  8,192,000
        else if (s == (long long)BATCH * HW2 * NC) c2 = (const float*)p;  //  2,048,000
        else if (s == (long long)BATCH * HW0 * 4)  r0 = (const float*)p;  //  1,638,400
        else if (s == (long long)BATCH * HW1 * 4)  r1 = (const float*)p;  //    409,600
        else if (s == (long long)BATCH * HW2 * 4)  r2 = (const float*)p;  //    102,400
        else if (s == (long long)BATCH * NGT * 4)  gt = (const float*)p;  //      8,192
        else if (s == (long long)BATCH * NGT)      lb = (const int*)p;    //      2,048
    }
    float* out = (float*)d_out;

    argmin_kernel<<<BATCH * CPB, 128>>>(r0, r1, r2, gt);
    gather_kernel<<<GBLK, 256>>>(c0, c1, c2, r0, r1, r2, gt, lb, out);
}